// round 13
// baseline (speedup 1.0000x reference)
#include <cuda_runtime.h>

// Hybrid quantum model, v11: v10 (rank-2 sector sim, q0 in packed lanes,
// light-cone tables) + single-wave occupancy (occ 3) + parallel finalize
// (128-thread gather via SMEM atomics instead of serial per-lane loads).

#define NC   320

typedef unsigned long long u64;

__device__ float g_accB[8*16];       // [bucket][batch*2+j] partial logits
__device__ unsigned int g_done;      // CTA completion counter

#define CU_A (-0.2705980500730985f)
#define CU_B ( 0.6532814824381883f)
#define R2   ( 0.7071067811865476f)

// ---------------- packed f32x2 helpers ----------------
__device__ __forceinline__ u64 pack2(float x, float y) {
    u64 u; asm("mov.b64 %0,{%1,%2};" : "=l"(u) : "f"(x), "f"(y)); return u;
}
__device__ __forceinline__ float2 unpk(u64 u) {
    float2 v; asm("mov.b64 {%0,%1},%2;" : "=f"(v.x), "=f"(v.y) : "l"(u)); return v;
}
__device__ __forceinline__ u64 bc(float x) { return pack2(x, x); }
__device__ __forceinline__ u64 ffma2(u64 a, u64 b, u64 c) {
    u64 d; asm("fma.rn.f32x2 %0,%1,%2,%3;" : "=l"(d) : "l"(a), "l"(b), "l"(c)); return d;
}
__device__ __forceinline__ u64 fmul2(u64 a, u64 b) {
    u64 d; asm("mul.rn.f32x2 %0,%1,%2;" : "=l"(d) : "l"(a), "l"(b)); return d;
}
__device__ __forceinline__ u64 neg2(u64 a) { return a ^ 0x8000000080000000ull; }

__device__ __forceinline__ float2 cmul(float2 a, float2 b) {
    return make_float2(a.x*b.x - a.y*b.y, a.x*b.y + a.y*b.x);
}
__device__ __forceinline__ float2 cadd(float2 a, float2 b) {
    return make_float2(a.x + b.x, a.y + b.y);
}

// MPS transfer factor (validated): h(0,*)=1/sqrt2; h(1,0)=(-A,-B); h(1,1)=(B,-A)
__device__ __forceinline__ float2 hfun(int xb, int yb) {
    if (xb == 0) return make_float2(R2, 0.0f);
    return yb ? make_float2(CU_B, -CU_A)
              : make_float2(-CU_A, -CU_B);
}

// shfl half-butterfly, coefficients prebuilt as u64 (may differ per f32x2 lane)
__device__ __forceinline__ void gate_u64(u64& vr, u64& vi, int t, int mask,
                                         u64 px, u64 py, u64 qx, u64 qy) {
    u64 or_ = __shfl_xor_sync(0xffffffffu, vr, mask);
    u64 oi_ = __shfl_xor_sync(0xffffffffu, vi, mask);
    bool tb = (t & mask) != 0;
    u64 ar = tb ? or_ : vr,  ai = tb ? oi_ : vi;
    u64 br = tb ? vr  : or_, bi = tb ? vi  : oi_;
    u64 ti = ffma2(py, ai, fmul2(qy, bi));
    vr = ffma2(px, ar, ffma2(qx, br, neg2(ti)));
    vi = ffma2(py, ar, ffma2(px, ai, ffma2(qy, br, fmul2(qx, bi))));
}

// lane-internal complex 2x2 on the f32x2 components (q0 gate)
__device__ __forceinline__ void lane_bfly(u64& r, u64& i,
        float x00, float y00, float x01, float y01,
        float x10, float y10, float x11, float y11) {
    float2 rr = unpk(r), ii = unpk(i);
    float ax = rr.x, bx = rr.y, ay = ii.x, by = ii.y;
    float nax = x00*ax - y00*ay + x01*bx - y01*by;
    float nay = y00*ax + x00*ay + y01*bx + x01*by;
    float nbx = x10*ax - y10*ay + x11*bx - y11*by;
    float nby = y10*ax + x10*ay + y11*bx + x11*by;
    r = pack2(nax, nbx); i = pack2(nay, nby);
}

// light-cone (l,q) pairs needing R/UR tables (q>=1)
__device__ __constant__ int LQ_L[10] = {0,0,0,0,1,1,1,2,2,3};
__device__ __constant__ int LQ_Q[10] = {1,2,3,4,1,2,3,1,2,1};

__global__ void __launch_bounds__(256, 3)
qsim_kernel(const float* __restrict__ x,  const float* __restrict__ W1,
            const float* __restrict__ b1, const float* __restrict__ qw,
            const float* __restrict__ W2, const float* __restrict__ b2,
            float* __restrict__ out)
{
    __shared__ float2 R0f[5*4];    // R_{l,0}, l=0..4
    __shared__ float2 Rq[10*4];    // cone R_{l,q}
    __shared__ float2 URq[10*4];   // cone U*R_{l,q}
    __shared__ float  facc[16];
    __shared__ unsigned int lastf;

    const int tid = threadIdx.x;
    const int s   = tid >> 5;      // warp = batch row 0..7
    const int t   = tid & 31;
    const int c   = blockIdx.x;    // circuit

    // ---- table prep: only the 15 light-cone matrices ----
    if (tid < 15) {
        int l, q;
        if (tid < 5) { l = tid; q = 0; }
        else         { l = LQ_L[tid-5]; q = LQ_Q[tid-5]; }
        const float* wp = qw + ((c*5 + l)*10 + q) * 3;
        float w0 = wp[0], w1v = wp[1], w2v = wp[2];
        float sy, cy; __sincosf(0.5f * w1v,        &sy, &cy);
        float sp, cp; __sincosf(0.5f * (w0 + w2v), &sp, &cp);
        float sm, cm; __sincosf(0.5f * (w0 - w2v), &sm, &cm);
        float2 r00 = make_float2( cy*cp, -cy*sp);
        float2 r01 = make_float2(-sy*cm, -sy*sm);
        float2 r10 = make_float2( sy*cm, -sy*sm);
        float2 r11 = make_float2( cy*cp,  cy*sp);
        if (tid < 5) {
            R0f[tid*4+0]=r00; R0f[tid*4+1]=r01; R0f[tid*4+2]=r10; R0f[tid*4+3]=r11;
        } else {
            int pi = tid - 5;
            Rq[pi*4+0]=r00; Rq[pi*4+1]=r01; Rq[pi*4+2]=r10; Rq[pi*4+3]=r11;
        }
    }
    __syncthreads();
    if (tid < 10) {
        const float2 u00 = make_float2(CU_A,  CU_A);
        const float2 u01 = make_float2(CU_B, -CU_B);
        const float2 u10 = make_float2(CU_B,  CU_B);
        const float2 u11 = make_float2(-CU_A, CU_A);
        float2 r00 = Rq[tid*4+0], r01 = Rq[tid*4+1], r10 = Rq[tid*4+2], r11 = Rq[tid*4+3];
        URq[tid*4+0] = cadd(cmul(u00, r00), cmul(u01, r10));
        URq[tid*4+1] = cadd(cmul(u00, r01), cmul(u01, r11));
        URq[tid*4+2] = cadd(cmul(u10, r00), cmul(u11, r10));
        URq[tid*4+3] = cadd(cmul(u10, r01), cmul(u11, r11));
    }

    float hang = x[s*2+0]*W1[c*2+0] + x[s*2+1]*W1[c*2+1] + b1[c];
    float se, ce;
    __sincosf(0.5f * hang, &se, &ce);

    // layout: packed f32x2 = a4 (q0) in {0,1}; lane bit4 = sector b4;
    //         lane bits 3..0 = a3..a0 (qubits 1..4)
    const int t4 = (t >> 4) & 1;
    const int t3 = (t >> 3) & 1, t2 = (t >> 2) & 1, t1b = (t >> 1) & 1, t0 = t & 1;

    // ---- init: amp = E(a4) h(a4,a3) [h(a3,a2)h(a2,a1)h(a1,a0)h(a0,b4)] ----
    u64 vr, vi;
    {
        float2 C = cmul(cmul(hfun(t3,t2), hfun(t2,t1b)),
                        cmul(hfun(t1b,t0), hfun(t0,t4)));
        float E0 = (ce - se) * R2, E1 = (ce + se) * R2;
        float2 D = cmul(hfun(1, t3), C);       // comp1 chain head
        float s0 = E0 * R2;                    // comp0: h(0,a3) = (R2,0)
        vr = pack2(s0 * C.x, E1 * D.x);
        vi = pack2(s0 * C.y, E1 * D.y);
    }

    __syncthreads();   // tables visible

    // ---- light-cone pruned layers 1..4 (fully unrolled) ----
    const int PB[4] = {0, 4, 7, 9};
#pragma unroll
    for (int l = 1; l <= 4; ++l) {
        const int B = PB[l-1];

        // merged embedding E' = emb_l * R_{l-1,0} on q0: lane-internal
        {
            const float2* Rp0 = R0f + (l-1)*4;
            float2 r00 = Rp0[0], r01 = Rp0[1], r10 = Rp0[2], r11 = Rp0[3];
            float2 e00, e01, e10, e11;
            if ((l & 1) == 0) {  // RY (real)
                e00 = make_float2(ce*r00.x - se*r10.x, ce*r00.y - se*r10.y);
                e01 = make_float2(ce*r01.x - se*r11.x, ce*r01.y - se*r11.y);
                e10 = make_float2(se*r00.x + ce*r10.x, se*r00.y + ce*r10.y);
                e11 = make_float2(se*r01.x + ce*r11.x, se*r01.y + ce*r11.y);
            } else {             // RZ diag((ce,-se),(ce,se))
                float2 f0 = make_float2(ce, -se), f1 = make_float2(ce, se);
                e00 = cmul(f0, r00); e01 = cmul(f0, r01);
                e10 = cmul(f1, r10); e11 = cmul(f1, r11);
            }
            lane_bfly(vr, vi, e00.x,e00.y, e01.x,e01.y, e10.x,e10.y, e11.x,e11.y);
        }
        // M(0,1): ctrl q0 (packed: comp0->R, comp1->UR), tgt q1 = bit3
        {
            const float2* Rb = Rq  + (B+0)*4;
            const float2* Ub = URq + (B+0)*4;
            int r = t3 ? 2 : 0;
            float2 Rp = Rb[r], Rqe = Rb[r+1], Up = Ub[r], Uq = Ub[r+1];
            gate_u64(vr, vi, t, 8,
                     pack2(Rp.x, Up.x), pack2(Rp.y, Up.y),
                     pack2(Rqe.x, Uq.x), pack2(Rqe.y, Uq.y));
        }
        if (l <= 3) {  // M(1,2): ctrl bit3, tgt bit2
            const float2* base = (t3 ? URq : Rq) + (B+1)*4;
            int r = t2 ? 2 : 0;
            float2 p = base[r], q = base[r+1];
            gate_u64(vr, vi, t, 4, bc(p.x), bc(p.y), bc(q.x), bc(q.y));
        }
        if (l <= 2) {  // M(2,3): ctrl bit2, tgt bit1
            const float2* base = (t2 ? URq : Rq) + (B+2)*4;
            int r = t1b ? 2 : 0;
            float2 p = base[r], q = base[r+1];
            gate_u64(vr, vi, t, 2, bc(p.x), bc(p.y), bc(q.x), bc(q.y));
        }
        if (l == 1) {  // M(3,4): ctrl bit1, tgt bit0
            const float2* base = (t1b ? URq : Rq) + (B+3)*4;
            int r = t0 ? 2 : 0;
            float2 p = base[r], q = base[r+1];
            gate_u64(vr, vi, t, 1, bc(p.x), bc(p.y), bc(q.x), bc(q.y));
        }
    }

    // ===== Measurement: <Z0>, trailing q0 gate G = H * R40 * R40 (lane-internal)
    {
        float2 r00 = R0f[16], r01 = R0f[17], r10 = R0f[18], r11 = R0f[19];
        float2 s00 = cadd(cmul(r00,r00), cmul(r01,r10));
        float2 s01 = cadd(cmul(r00,r01), cmul(r01,r11));
        float2 s10 = cadd(cmul(r10,r00), cmul(r11,r10));
        float2 s11 = cadd(cmul(r10,r01), cmul(r11,r11));
        float2 g00 = make_float2(R2*(s00.x+s10.x), R2*(s00.y+s10.y));
        float2 g01 = make_float2(R2*(s01.x+s11.x), R2*(s01.y+s11.y));
        float2 g10 = make_float2(R2*(s00.x-s10.x), R2*(s00.y-s10.y));
        float2 g11 = make_float2(R2*(s01.x-s11.x), R2*(s01.y-s11.y));
        lane_bfly(vr, vi, g00.x,g00.y, g01.x,g01.y, g10.x,g10.y, g11.x,g11.y);

        float2 rr = unpk(vr), ii = unpk(vi);
        float z = (rr.x*rr.x + ii.x*ii.x) - (rr.y*rr.y + ii.y*ii.y);
#pragma unroll
        for (int off = 16; off > 0; off >>= 1)
            z += __shfl_down_sync(0xffffffffu, z, off);

        if (t == 0) {   // warp leader: bucketed accumulation
            int bucket = (blockIdx.x ^ s) & 7;
            atomicAdd(&g_accB[bucket*16 + s*2 + 0], z * W2[c]);
            atomicAdd(&g_accB[bucket*16 + s*2 + 1], z * W2[NC + c]);
        }
    }
    __syncthreads();

    // last CTA finalizes: parallel gather via SMEM atomics, softmax, reset
    if (tid == 0) {
        __threadfence();
        lastf = (atomicAdd(&g_done, 1u) == gridDim.x - 1) ? 1u : 0u;
        __threadfence();
    }
    __syncthreads();
    if (lastf) {
        if (tid < 16) facc[tid] = b2[tid & 1];
        __syncthreads();
        if (tid < 128) atomicAdd(&facc[tid & 15], g_accB[tid]);
        __syncthreads();
        if (tid < 16) {
            float v = facc[tid];
            float o = __shfl_xor_sync(0x0000ffffu, v, 1);
            float m = fmaxf(v, o);
            float e = expf(v - m), eo = expf(o - m);
            out[tid] = e / (e + eo);
        }
        if (tid < 128) g_accB[tid] = 0.0f;
        if (tid == 0) { g_done = 0u; __threadfence(); }
    }
}

extern "C" void kernel_launch(void* const* d_in, const int* in_sizes, int n_in,
                              void* d_out, int out_size) {
    const float* x  = (const float*)d_in[0];   // (8,2)
    const float* W1 = (const float*)d_in[1];   // (320,2)
    const float* b1 = (const float*)d_in[2];   // (320,)
    const float* qw = (const float*)d_in[3];   // (320,5,10,3)
    const float* W2 = (const float*)d_in[4];   // (2,320)
    const float* b2 = (const float*)d_in[5];   // (2,)
    float* out = (float*)d_out;                // (8,2)

    qsim_kernel<<<320, 256>>>(x, W1, b1, qw, W2, b2, out);
}

// round 14
// speedup vs baseline: 1.0904x; 1.0904x over previous
#include <cuda_runtime.h>

// Hybrid quantum model, v12: v11 math with all per-warp-redundant work hoisted
// to parallel CTA prep: lane-init constants (K0/K1), merged embedding matrices
// E'(l,s), measurement matrix G, and per-batch E0/E1 all built once in SMEM.
// Warp body: 1 init load + 4 embedding lane_bflys + 10 shfl gates + measure.

#define NC   320

typedef unsigned long long u64;

__device__ float g_accB[8*16];       // [bucket][batch*2+j] partial logits
__device__ unsigned int g_done;      // CTA completion counter

#define CU_A (-0.2705980500730985f)
#define CU_B ( 0.6532814824381883f)
#define R2   ( 0.7071067811865476f)

// ---------------- packed f32x2 helpers ----------------
__device__ __forceinline__ u64 pack2(float x, float y) {
    u64 u; asm("mov.b64 %0,{%1,%2};" : "=l"(u) : "f"(x), "f"(y)); return u;
}
__device__ __forceinline__ float2 unpk(u64 u) {
    float2 v; asm("mov.b64 {%0,%1},%2;" : "=f"(v.x), "=f"(v.y) : "l"(u)); return v;
}
__device__ __forceinline__ u64 bc(float x) { return pack2(x, x); }
__device__ __forceinline__ u64 ffma2(u64 a, u64 b, u64 c) {
    u64 d; asm("fma.rn.f32x2 %0,%1,%2,%3;" : "=l"(d) : "l"(a), "l"(b), "l"(c)); return d;
}
__device__ __forceinline__ u64 fmul2(u64 a, u64 b) {
    u64 d; asm("mul.rn.f32x2 %0,%1,%2;" : "=l"(d) : "l"(a), "l"(b)); return d;
}
__device__ __forceinline__ u64 neg2(u64 a) { return a ^ 0x8000000080000000ull; }

__device__ __forceinline__ float2 cmul(float2 a, float2 b) {
    return make_float2(a.x*b.x - a.y*b.y, a.x*b.y + a.y*b.x);
}
__device__ __forceinline__ float2 cadd(float2 a, float2 b) {
    return make_float2(a.x + b.x, a.y + b.y);
}

// MPS transfer factor (validated): h(0,*)=1/sqrt2; h(1,0)=(-A,-B); h(1,1)=(B,-A)
__device__ __forceinline__ float2 hfun(int xb, int yb) {
    if (xb == 0) return make_float2(R2, 0.0f);
    return yb ? make_float2(CU_B, -CU_A)
              : make_float2(-CU_A, -CU_B);
}

// shfl half-butterfly, coefficients prebuilt as u64 (may differ per f32x2 lane)
__device__ __forceinline__ void gate_u64(u64& vr, u64& vi, int t, int mask,
                                         u64 px, u64 py, u64 qx, u64 qy) {
    u64 or_ = __shfl_xor_sync(0xffffffffu, vr, mask);
    u64 oi_ = __shfl_xor_sync(0xffffffffu, vi, mask);
    bool tb = (t & mask) != 0;
    u64 ar = tb ? or_ : vr,  ai = tb ? oi_ : vi;
    u64 br = tb ? vr  : or_, bi = tb ? vi  : oi_;
    u64 ti = ffma2(py, ai, fmul2(qy, bi));
    vr = ffma2(px, ar, ffma2(qx, br, neg2(ti)));
    vi = ffma2(py, ar, ffma2(px, ai, ffma2(qy, br, fmul2(qx, bi))));
}

// lane-internal complex 2x2 on the f32x2 components (q0 gate)
__device__ __forceinline__ void lane_bfly(u64& r, u64& i,
        float x00, float y00, float x01, float y01,
        float x10, float y10, float x11, float y11) {
    float2 rr = unpk(r), ii = unpk(i);
    float ax = rr.x, bx = rr.y, ay = ii.x, by = ii.y;
    float nax = x00*ax - y00*ay + x01*bx - y01*by;
    float nay = y00*ax + x00*ay + y01*bx + x01*by;
    float nbx = x10*ax - y10*ay + x11*bx - y11*by;
    float nby = y10*ax + x10*ay + y11*bx + x11*by;
    r = pack2(nax, nbx); i = pack2(nay, nby);
}

// light-cone (l,q) pairs needing R/UR tables (q>=1)
__device__ __constant__ int LQ_L[10] = {0,0,0,0,1,1,1,2,2,3};
__device__ __constant__ int LQ_Q[10] = {1,2,3,4,1,2,3,1,2,1};

__global__ void __launch_bounds__(256, 3)
qsim_kernel(const float* __restrict__ x,  const float* __restrict__ W1,
            const float* __restrict__ b1, const float* __restrict__ qw,
            const float* __restrict__ W2, const float* __restrict__ b2,
            float* __restrict__ out)
{
    __shared__ float2 R0f[5*4];      // R_{l,0}, l=0..4
    __shared__ float2 Rq[10*4];      // cone R_{l,q}
    __shared__ float2 URq[10*4];     // cone U*R_{l,q}
    __shared__ float4 Kin[32];       // lane init constants {K0.x,K0.y,K1.x,K1.y}
    __shared__ float2 Esh[8];        // per-batch {E0, E1}
    __shared__ float4 Em[4][8][2];   // merged embedding E'(l,s), 2x float4
    __shared__ float4 Gm[2];         // measurement matrix G
    __shared__ float  facc[16];
    __shared__ unsigned int lastf;

    const int tid = threadIdx.x;
    const int s   = tid >> 5;      // warp = batch row 0..7
    const int t   = tid & 31;
    const int c   = blockIdx.x;    // circuit

    // ---- stage 1: the 15 light-cone R matrices ----
    if (tid < 15) {
        int l, q;
        if (tid < 5) { l = tid; q = 0; }
        else         { l = LQ_L[tid-5]; q = LQ_Q[tid-5]; }
        const float* wp = qw + ((c*5 + l)*10 + q) * 3;
        float w0 = wp[0], w1v = wp[1], w2v = wp[2];
        float sy, cy; __sincosf(0.5f * w1v,        &sy, &cy);
        float sp, cp; __sincosf(0.5f * (w0 + w2v), &sp, &cp);
        float sm, cm; __sincosf(0.5f * (w0 - w2v), &sm, &cm);
        float2 r00 = make_float2( cy*cp, -cy*sp);
        float2 r01 = make_float2(-sy*cm, -sy*sm);
        float2 r10 = make_float2( sy*cm, -sy*sm);
        float2 r11 = make_float2( cy*cp,  cy*sp);
        if (tid < 5) {
            R0f[tid*4+0]=r00; R0f[tid*4+1]=r01; R0f[tid*4+2]=r10; R0f[tid*4+3]=r11;
        } else {
            int pi = tid - 5;
            Rq[pi*4+0]=r00; Rq[pi*4+1]=r01; Rq[pi*4+2]=r10; Rq[pi*4+3]=r11;
        }
    }
    // lane init constants (no deps): K0 = R2*C, K1 = h(1,b3)*C
    if (tid >= 96 && tid < 128) {
        int tt = tid - 96;
        int b4 = (tt >> 4) & 1, b3 = (tt >> 3) & 1, b2i = (tt >> 2) & 1,
            b1i = (tt >> 1) & 1, b0 = tt & 1;
        float2 C = cmul(cmul(hfun(b3,b2i), hfun(b2i,b1i)),
                        cmul(hfun(b1i,b0), hfun(b0,b4)));
        float2 K1 = cmul(hfun(1, b3), C);
        Kin[tt] = make_float4(R2*C.x, R2*C.y, K1.x, K1.y);
    }
    __syncthreads();

    // ---- stage 2 (parallel): UR, E'(l,s)+Esh, G ----
    if (tid < 10) {
        const float2 u00 = make_float2(CU_A,  CU_A);
        const float2 u01 = make_float2(CU_B, -CU_B);
        const float2 u10 = make_float2(CU_B,  CU_B);
        const float2 u11 = make_float2(-CU_A, CU_A);
        float2 r00 = Rq[tid*4+0], r01 = Rq[tid*4+1], r10 = Rq[tid*4+2], r11 = Rq[tid*4+3];
        URq[tid*4+0] = cadd(cmul(u00, r00), cmul(u01, r10));
        URq[tid*4+1] = cadd(cmul(u00, r01), cmul(u01, r11));
        URq[tid*4+2] = cadd(cmul(u10, r00), cmul(u11, r10));
        URq[tid*4+3] = cadd(cmul(u10, r01), cmul(u11, r11));
    } else if (tid >= 32 && tid < 64) {
        int lidx = (tid - 32) >> 3;      // layer l = lidx+1
        int s2   = (tid - 32) & 7;       // batch row
        float hang = x[s2*2+0]*W1[c*2+0] + x[s2*2+1]*W1[c*2+1] + b1[c];
        float se, ce; __sincosf(0.5f * hang, &se, &ce);
        if (lidx == 0) Esh[s2] = make_float2((ce - se) * R2, (ce + se) * R2);
        const float2* Rp0 = R0f + lidx*4;
        float2 r00 = Rp0[0], r01 = Rp0[1], r10 = Rp0[2], r11 = Rp0[3];
        float2 e00, e01, e10, e11;
        if (((lidx + 1) & 1) == 0) {  // even layer: RY (real)
            e00 = make_float2(ce*r00.x - se*r10.x, ce*r00.y - se*r10.y);
            e01 = make_float2(ce*r01.x - se*r11.x, ce*r01.y - se*r11.y);
            e10 = make_float2(se*r00.x + ce*r10.x, se*r00.y + ce*r10.y);
            e11 = make_float2(se*r01.x + ce*r11.x, se*r01.y + ce*r11.y);
        } else {                      // odd layer: RZ diag((ce,-se),(ce,se))
            float2 f0 = make_float2(ce, -se), f1 = make_float2(ce, se);
            e00 = cmul(f0, r00); e01 = cmul(f0, r01);
            e10 = cmul(f1, r10); e11 = cmul(f1, r11);
        }
        Em[lidx][s2][0] = make_float4(e00.x, e00.y, e01.x, e01.y);
        Em[lidx][s2][1] = make_float4(e10.x, e10.y, e11.x, e11.y);
    } else if (tid == 64) {
        // G = H * R40 * R40 (batch-independent)
        float2 r00 = R0f[16], r01 = R0f[17], r10 = R0f[18], r11 = R0f[19];
        float2 s00 = cadd(cmul(r00,r00), cmul(r01,r10));
        float2 s01 = cadd(cmul(r00,r01), cmul(r01,r11));
        float2 s10 = cadd(cmul(r10,r00), cmul(r11,r10));
        float2 s11 = cadd(cmul(r10,r01), cmul(r11,r11));
        Gm[0] = make_float4(R2*(s00.x+s10.x), R2*(s00.y+s10.y),
                            R2*(s01.x+s11.x), R2*(s01.y+s11.y));
        Gm[1] = make_float4(R2*(s00.x-s10.x), R2*(s00.y-s10.y),
                            R2*(s01.x-s11.x), R2*(s01.y-s11.y));
    }
    __syncthreads();

    // ---- warp body: init from tables ----
    const int t3 = (t >> 3) & 1, t2b = (t >> 2) & 1, t1b = (t >> 1) & 1, t0 = t & 1;
    u64 vr, vi;
    {
        float4 K = Kin[t];
        float2 E = Esh[s];
        vr = pack2(E.x * K.x, E.y * K.z);
        vi = pack2(E.x * K.y, E.y * K.w);
    }

    // ---- light-cone pruned layers 1..4 (fully unrolled) ----
    const int PB[4] = {0, 4, 7, 9};
#pragma unroll
    for (int l = 1; l <= 4; ++l) {
        const int B = PB[l-1];

        // merged embedding: preloaded matrix, lane-internal
        {
            float4 ea = Em[l-1][s][0], eb = Em[l-1][s][1];
            lane_bfly(vr, vi, ea.x,ea.y, ea.z,ea.w, eb.x,eb.y, eb.z,eb.w);
        }
        // M(0,1): ctrl q0 (packed: comp0->R, comp1->UR), tgt q1 = bit3
        {
            const float2* Rb = Rq  + (B+0)*4;
            const float2* Ub = URq + (B+0)*4;
            int r = t3 ? 2 : 0;
            float2 Rp = Rb[r], Rqe = Rb[r+1], Up = Ub[r], Uq = Ub[r+1];
            gate_u64(vr, vi, t, 8,
                     pack2(Rp.x, Up.x), pack2(Rp.y, Up.y),
                     pack2(Rqe.x, Uq.x), pack2(Rqe.y, Uq.y));
        }
        if (l <= 3) {  // M(1,2): ctrl bit3, tgt bit2
            const float2* base = (t3 ? URq : Rq) + (B+1)*4;
            int r = t2b ? 2 : 0;
            float2 p = base[r], q = base[r+1];
            gate_u64(vr, vi, t, 4, bc(p.x), bc(p.y), bc(q.x), bc(q.y));
        }
        if (l <= 2) {  // M(2,3): ctrl bit2, tgt bit1
            const float2* base = (t2b ? URq : Rq) + (B+2)*4;
            int r = t1b ? 2 : 0;
            float2 p = base[r], q = base[r+1];
            gate_u64(vr, vi, t, 2, bc(p.x), bc(p.y), bc(q.x), bc(q.y));
        }
        if (l == 1) {  // M(3,4): ctrl bit1, tgt bit0
            const float2* base = (t1b ? URq : Rq) + (B+3)*4;
            int r = t0 ? 2 : 0;
            float2 p = base[r], q = base[r+1];
            gate_u64(vr, vi, t, 1, bc(p.x), bc(p.y), bc(q.x), bc(q.y));
        }
    }

    // ===== Measurement: <Z0>, trailing q0 gate G (preloaded, lane-internal)
    {
        float4 ga = Gm[0], gb = Gm[1];
        lane_bfly(vr, vi, ga.x,ga.y, ga.z,ga.w, gb.x,gb.y, gb.z,gb.w);

        float2 rr = unpk(vr), ii = unpk(vi);
        float z = (rr.x*rr.x + ii.x*ii.x) - (rr.y*rr.y + ii.y*ii.y);
#pragma unroll
        for (int off = 16; off > 0; off >>= 1)
            z += __shfl_down_sync(0xffffffffu, z, off);

        if (t == 0) {   // warp leader: bucketed accumulation
            int bucket = (blockIdx.x ^ s) & 7;
            atomicAdd(&g_accB[bucket*16 + s*2 + 0], z * W2[c]);
            atomicAdd(&g_accB[bucket*16 + s*2 + 1], z * W2[NC + c]);
        }
    }
    __syncthreads();

    // last CTA finalizes: parallel gather via SMEM atomics, softmax, reset
    if (tid == 0) {
        __threadfence();
        lastf = (atomicAdd(&g_done, 1u) == gridDim.x - 1) ? 1u : 0u;
        __threadfence();
    }
    __syncthreads();
    if (lastf) {
        if (tid < 16) facc[tid] = b2[tid & 1];
        __syncthreads();
        if (tid < 128) atomicAdd(&facc[tid & 15], g_accB[tid]);
        __syncthreads();
        if (tid < 16) {
            float v = facc[tid];
            float o = __shfl_xor_sync(0x0000ffffu, v, 1);
            float m = fmaxf(v, o);
            float e = expf(v - m), eo = expf(o - m);
            out[tid] = e / (e + eo);
        }
        if (tid < 128) g_accB[tid] = 0.0f;
        if (tid == 0) { g_done = 0u; __threadfence(); }
    }
}

extern "C" void kernel_launch(void* const* d_in, const int* in_sizes, int n_in,
                              void* d_out, int out_size) {
    const float* x  = (const float*)d_in[0];   // (8,2)
    const float* W1 = (const float*)d_in[1];   // (320,2)
    const float* b1 = (const float*)d_in[2];   // (320,)
    const float* qw = (const float*)d_in[3];   // (320,5,10,3)
    const float* W2 = (const float*)d_in[4];   // (2,320)
    const float* b2 = (const float*)d_in[5];   // (2,)
    float* out = (float*)d_out;                // (8,2)

    qsim_kernel<<<320, 256>>>(x, W1, b1, qw, W2, b2, out);
}

// round 16
// speedup vs baseline: 1.1029x; 1.0114x over previous
#include <cuda_runtime.h>

// Hybrid quantum model, v13: v12 math, 2 circuits per CTA as parallel warp
// groups (grid 160 x block 512) to halve CTA dispatch ramp; single prep
// barrier (each prep thread computes its own R_{l,0} redundantly).

#define NC   320

typedef unsigned long long u64;

__device__ float g_accB[8*16];       // [bucket][batch*2+j] partial logits
__device__ unsigned int g_done;      // CTA completion counter

#define CU_A (-0.2705980500730985f)
#define CU_B ( 0.6532814824381883f)
#define R2   ( 0.7071067811865476f)

// ---------------- packed f32x2 helpers ----------------
__device__ __forceinline__ u64 pack2(float x, float y) {
    u64 u; asm("mov.b64 %0,{%1,%2};" : "=l"(u) : "f"(x), "f"(y)); return u;
}
__device__ __forceinline__ float2 unpk(u64 u) {
    float2 v; asm("mov.b64 {%0,%1},%2;" : "=f"(v.x), "=f"(v.y) : "l"(u)); return v;
}
__device__ __forceinline__ u64 bc(float x) { return pack2(x, x); }
__device__ __forceinline__ u64 ffma2(u64 a, u64 b, u64 c) {
    u64 d; asm("fma.rn.f32x2 %0,%1,%2,%3;" : "=l"(d) : "l"(a), "l"(b), "l"(c)); return d;
}
__device__ __forceinline__ u64 fmul2(u64 a, u64 b) {
    u64 d; asm("mul.rn.f32x2 %0,%1,%2;" : "=l"(d) : "l"(a), "l"(b)); return d;
}
__device__ __forceinline__ u64 neg2(u64 a) { return a ^ 0x8000000080000000ull; }

__device__ __forceinline__ float2 cmul(float2 a, float2 b) {
    return make_float2(a.x*b.x - a.y*b.y, a.x*b.y + a.y*b.x);
}
__device__ __forceinline__ float2 cadd(float2 a, float2 b) {
    return make_float2(a.x + b.x, a.y + b.y);
}

// MPS transfer factor (validated): h(0,*)=1/sqrt2; h(1,0)=(-A,-B); h(1,1)=(B,-A)
__device__ __forceinline__ float2 hfun(int xb, int yb) {
    if (xb == 0) return make_float2(R2, 0.0f);
    return yb ? make_float2(CU_B, -CU_A)
              : make_float2(-CU_A, -CU_B);
}

// build rot matrix R = RZ(w2) RY(w1) RZ(w0) from 3 angles
__device__ __forceinline__ void rotmat(const float* wp, float2& r00, float2& r01,
                                       float2& r10, float2& r11) {
    float w0 = wp[0], w1v = wp[1], w2v = wp[2];
    float sy, cy; __sincosf(0.5f * w1v,        &sy, &cy);
    float sp, cp; __sincosf(0.5f * (w0 + w2v), &sp, &cp);
    float sm, cm; __sincosf(0.5f * (w0 - w2v), &sm, &cm);
    r00 = make_float2( cy*cp, -cy*sp);
    r01 = make_float2(-sy*cm, -sy*sm);
    r10 = make_float2( sy*cm, -sy*sm);
    r11 = make_float2( cy*cp,  cy*sp);
}

// shfl half-butterfly, coefficients prebuilt as u64 (may differ per f32x2 lane)
__device__ __forceinline__ void gate_u64(u64& vr, u64& vi, int t, int mask,
                                         u64 px, u64 py, u64 qx, u64 qy) {
    u64 or_ = __shfl_xor_sync(0xffffffffu, vr, mask);
    u64 oi_ = __shfl_xor_sync(0xffffffffu, vi, mask);
    bool tb = (t & mask) != 0;
    u64 ar = tb ? or_ : vr,  ai = tb ? oi_ : vi;
    u64 br = tb ? vr  : or_, bi = tb ? vi  : oi_;
    u64 ti = ffma2(py, ai, fmul2(qy, bi));
    vr = ffma2(px, ar, ffma2(qx, br, neg2(ti)));
    vi = ffma2(py, ar, ffma2(px, ai, ffma2(qy, br, fmul2(qx, bi))));
}

// lane-internal complex 2x2 on the f32x2 components (q0 gate)
__device__ __forceinline__ void lane_bfly(u64& r, u64& i,
        float x00, float y00, float x01, float y01,
        float x10, float y10, float x11, float y11) {
    float2 rr = unpk(r), ii = unpk(i);
    float ax = rr.x, bx = rr.y, ay = ii.x, by = ii.y;
    float nax = x00*ax - y00*ay + x01*bx - y01*by;
    float nay = y00*ax + x00*ay + y01*bx + x01*by;
    float nbx = x10*ax - y10*ay + x11*bx - y11*by;
    float nby = y10*ax + x10*ay + y11*bx + x11*by;
    r = pack2(nax, nbx); i = pack2(nay, nby);
}

// light-cone (l,q) pairs needing R/UR tables (q>=1)
__device__ __constant__ int LQ_L[10] = {0,0,0,0,1,1,1,2,2,3};
__device__ __constant__ int LQ_Q[10] = {1,2,3,4,1,2,3,1,2,1};

__global__ void __launch_bounds__(512, 2)
qsim_kernel(const float* __restrict__ x,  const float* __restrict__ W1,
            const float* __restrict__ b1, const float* __restrict__ qw,
            const float* __restrict__ W2, const float* __restrict__ b2,
            float* __restrict__ out)
{
    __shared__ float2 Rq[2][10*4];    // cone R_{l,q}, per group
    __shared__ float2 URq[2][10*4];   // cone U*R_{l,q}
    __shared__ float4 Kin[32];        // lane init constants (circuit-indep)
    __shared__ float2 Esh[2][8];      // per-batch {E0, E1}
    __shared__ float4 Em[2][4][8][2]; // merged embedding E'(l,s)
    __shared__ float4 Gm[2][2];       // measurement matrix G
    __shared__ float  facc[16];
    __shared__ unsigned int lastf;

    const int tid = threadIdx.x;
    const int g   = tid >> 8;        // warp group = circuit slot 0/1
    const int tg  = tid & 255;       // thread within group
    const int s   = tg >> 5;         // warp = batch row 0..7
    const int t   = tid & 31;
    const int c   = blockIdx.x * 2 + g;  // circuit

    // ---- single-stage prep (all independent; one barrier) ----
    if (tg < 10) {
        // cone pair tg: R and UR
        int l = LQ_L[tg], q = LQ_Q[tg];
        float2 r00, r01, r10, r11;
        rotmat(qw + ((c*5 + l)*10 + q) * 3, r00, r01, r10, r11);
        Rq[g][tg*4+0]=r00; Rq[g][tg*4+1]=r01; Rq[g][tg*4+2]=r10; Rq[g][tg*4+3]=r11;
        const float2 u00 = make_float2(CU_A,  CU_A);
        const float2 u01 = make_float2(CU_B, -CU_B);
        const float2 u10 = make_float2(CU_B,  CU_B);
        const float2 u11 = make_float2(-CU_A, CU_A);
        URq[g][tg*4+0] = cadd(cmul(u00, r00), cmul(u01, r10));
        URq[g][tg*4+1] = cadd(cmul(u00, r01), cmul(u01, r11));
        URq[g][tg*4+2] = cadd(cmul(u10, r00), cmul(u11, r10));
        URq[g][tg*4+3] = cadd(cmul(u10, r01), cmul(u11, r11));
    } else if (tg >= 32 && tg < 64) {
        // E'(lidx+1, s2): own sincos for hang AND own R_{lidx,0}
        int lidx = (tg - 32) >> 3;
        int s2   = (tg - 32) & 7;
        float hang = x[s2*2+0]*W1[c*2+0] + x[s2*2+1]*W1[c*2+1] + b1[c];
        float se, ce; __sincosf(0.5f * hang, &se, &ce);
        if (lidx == 0) Esh[g][s2] = make_float2((ce - se) * R2, (ce + se) * R2);
        float2 r00, r01, r10, r11;
        rotmat(qw + ((c*5 + lidx)*10 + 0) * 3, r00, r01, r10, r11);
        float2 e00, e01, e10, e11;
        if (((lidx + 1) & 1) == 0) {  // even layer: RY (real)
            e00 = make_float2(ce*r00.x - se*r10.x, ce*r00.y - se*r10.y);
            e01 = make_float2(ce*r01.x - se*r11.x, ce*r01.y - se*r11.y);
            e10 = make_float2(se*r00.x + ce*r10.x, se*r00.y + ce*r10.y);
            e11 = make_float2(se*r01.x + ce*r11.x, se*r01.y + ce*r11.y);
        } else {                      // odd layer: RZ diag((ce,-se),(ce,se))
            float2 f0 = make_float2(ce, -se), f1 = make_float2(ce, se);
            e00 = cmul(f0, r00); e01 = cmul(f0, r01);
            e10 = cmul(f1, r10); e11 = cmul(f1, r11);
        }
        Em[g][lidx][s2][0] = make_float4(e00.x, e00.y, e01.x, e01.y);
        Em[g][lidx][s2][1] = make_float4(e10.x, e10.y, e11.x, e11.y);
    } else if (tg == 64) {
        // G = H * R40 * R40 (own R40)
        float2 r00, r01, r10, r11;
        rotmat(qw + ((c*5 + 4)*10 + 0) * 3, r00, r01, r10, r11);
        float2 s00 = cadd(cmul(r00,r00), cmul(r01,r10));
        float2 s01 = cadd(cmul(r00,r01), cmul(r01,r11));
        float2 s10 = cadd(cmul(r10,r00), cmul(r11,r10));
        float2 s11 = cadd(cmul(r10,r01), cmul(r11,r11));
        Gm[g][0] = make_float4(R2*(s00.x+s10.x), R2*(s00.y+s10.y),
                               R2*(s01.x+s11.x), R2*(s01.y+s11.y));
        Gm[g][1] = make_float4(R2*(s00.x-s10.x), R2*(s00.y-s10.y),
                               R2*(s01.x-s11.x), R2*(s01.y-s11.y));
    } else if (tid >= 96 && tid < 128) {
        // lane init constants (circuit-independent; group 0 builds them)
        int tt = tid - 96;
        int b4 = (tt >> 4) & 1, b3 = (tt >> 3) & 1, b2i = (tt >> 2) & 1,
            b1i = (tt >> 1) & 1, b0 = tt & 1;
        float2 C = cmul(cmul(hfun(b3,b2i), hfun(b2i,b1i)),
                        cmul(hfun(b1i,b0), hfun(b0,b4)));
        float2 K1 = cmul(hfun(1, b3), C);
        Kin[tt] = make_float4(R2*C.x, R2*C.y, K1.x, K1.y);
    }
    __syncthreads();

    // ---- warp body: init from tables ----
    const int t3 = (t >> 3) & 1, t2b = (t >> 2) & 1, t1b = (t >> 1) & 1, t0 = t & 1;
    u64 vr, vi;
    {
        float4 K = Kin[t];
        float2 E = Esh[g][s];
        vr = pack2(E.x * K.x, E.y * K.z);
        vi = pack2(E.x * K.y, E.y * K.w);
    }

    // ---- light-cone pruned layers 1..4 (fully unrolled) ----
    const int PB[4] = {0, 4, 7, 9};
#pragma unroll
    for (int l = 1; l <= 4; ++l) {
        const int B = PB[l-1];

        // merged embedding: preloaded matrix, lane-internal
        {
            float4 ea = Em[g][l-1][s][0], eb = Em[g][l-1][s][1];
            lane_bfly(vr, vi, ea.x,ea.y, ea.z,ea.w, eb.x,eb.y, eb.z,eb.w);
        }
        // M(0,1): ctrl q0 (packed: comp0->R, comp1->UR), tgt q1 = bit3
        {
            const float2* Rb = Rq[g]  + (B+0)*4;
            const float2* Ub = URq[g] + (B+0)*4;
            int r = t3 ? 2 : 0;
            float2 Rp = Rb[r], Rqe = Rb[r+1], Up = Ub[r], Uq = Ub[r+1];
            gate_u64(vr, vi, t, 8,
                     pack2(Rp.x, Up.x), pack2(Rp.y, Up.y),
                     pack2(Rqe.x, Uq.x), pack2(Rqe.y, Uq.y));
        }
        if (l <= 3) {  // M(1,2): ctrl bit3, tgt bit2
            const float2* base = (t3 ? URq[g] : Rq[g]) + (B+1)*4;
            int r = t2b ? 2 : 0;
            float2 p = base[r], q = base[r+1];
            gate_u64(vr, vi, t, 4, bc(p.x), bc(p.y), bc(q.x), bc(q.y));
        }
        if (l <= 2) {  // M(2,3): ctrl bit2, tgt bit1
            const float2* base = (t2b ? URq[g] : Rq[g]) + (B+2)*4;
            int r = t1b ? 2 : 0;
            float2 p = base[r], q = base[r+1];
            gate_u64(vr, vi, t, 2, bc(p.x), bc(p.y), bc(q.x), bc(q.y));
        }
        if (l == 1) {  // M(3,4): ctrl bit1, tgt bit0
            const float2* base = (t1b ? URq[g] : Rq[g]) + (B+3)*4;
            int r = t0 ? 2 : 0;
            float2 p = base[r], q = base[r+1];
            gate_u64(vr, vi, t, 1, bc(p.x), bc(p.y), bc(q.x), bc(q.y));
        }
    }

    // ===== Measurement: <Z0>, trailing q0 gate G (preloaded, lane-internal)
    {
        float4 ga = Gm[g][0], gb = Gm[g][1];
        lane_bfly(vr, vi, ga.x,ga.y, ga.z,ga.w, gb.x,gb.y, gb.z,gb.w);

        float2 rr = unpk(vr), ii = unpk(vi);
        float z = (rr.x*rr.x + ii.x*ii.x) - (rr.y*rr.y + ii.y*ii.y);
#pragma unroll
        for (int off = 16; off > 0; off >>= 1)
            z += __shfl_down_sync(0xffffffffu, z, off);

        if (t == 0) {   // warp leader: bucketed accumulation
            int bucket = ((blockIdx.x << 1) ^ g ^ s) & 7;
            atomicAdd(&g_accB[bucket*16 + s*2 + 0], z * W2[c]);
            atomicAdd(&g_accB[bucket*16 + s*2 + 1], z * W2[NC + c]);
        }
    }
    __syncthreads();

    // last CTA finalizes: parallel gather via SMEM atomics, softmax, reset
    if (tid == 0) {
        __threadfence();
        lastf = (atomicAdd(&g_done, 1u) == gridDim.x - 1) ? 1u : 0u;
        __threadfence();
    }
    __syncthreads();
    if (lastf) {
        if (tid < 16) facc[tid] = b2[tid & 1];
        __syncthreads();
        if (tid < 128) atomicAdd(&facc[tid & 15], g_accB[tid]);
        __syncthreads();
        if (tid < 16) {
            float v = facc[tid];
            float o = __shfl_xor_sync(0x0000ffffu, v, 1);
            float m = fmaxf(v, o);
            float e = expf(v - m), eo = expf(o - m);
            out[tid] = e / (e + eo);
        }
        if (tid < 128) g_accB[tid] = 0.0f;
        if (tid == 0) { g_done = 0u; __threadfence(); }
    }
}

extern "C" void kernel_launch(void* const* d_in, const int* in_sizes, int n_in,
                              void* d_out, int out_size) {
    const float* x  = (const float*)d_in[0];   // (8,2)
    const float* W1 = (const float*)d_in[1];   // (320,2)
    const float* b1 = (const float*)d_in[2];   // (320,)
    const float* qw = (const float*)d_in[3];   // (320,5,10,3)
    const float* W2 = (const float*)d_in[4];   // (2,320)
    const float* b2 = (const float*)d_in[5];   // (2,)
    float* out = (float*)d_out;                // (8,2)

    qsim_kernel<<<160, 512>>>(x, W1, b1, qw, W2, b2, out);
}